// round 13
// baseline (speedup 1.0000x reference)
#include <cuda_runtime.h>
#include <cuda_fp16.h>
#include <cstdint>

#define OUTC 11008
#define INC  4096
#define BATCH 512
#define BK 128                   // fused K-chunk (two 64-wide subtiles)
#define NCHUNK (INC / BK)        // 32
#define NT 512                   // 8 consumer warps + 8 producer warps
#define TM 64
#define TN 256
#define NBLK ((OUTC / TM) * (BATCH / TN))   // 344
#define NSTAGE 2

// ---- shared memory (byte offsets from 1024-aligned base) ----
#define SM_BAR   0                        // full[2] @0,8 ; empty[2] @16,24
#define SM_A     1024                     // 2 stages x 16 KB (2 x 8KB subtiles)
#define SM_B     (SM_A + NSTAGE * 16384)  // 33792, 2 stages x 64 KB (2 x 32KB subtiles)
#define SM_END   (SM_B + NSTAGE * 65536)  // 164864
#define SMEM_BYTES (SM_END + 1024)

__device__ __half g_xh[BATCH * INC];   // fp16 activations (4 MB, L2-resident)

#define SWZ(o) ((o) ^ (((o) >> 3) & 0x70))

__device__ __forceinline__ void cpa16(uint32_t dst, const void* src) {
    asm volatile("cp.async.cg.shared.global [%0], [%1], 16;" :: "r"(dst), "l"(src));
}

__device__ __forceinline__ float ex2(float x) {
    float r;
    asm("ex2.approx.ftz.f32 %0, %1;" : "=f"(r) : "f"(x));
    return r;
}

__device__ __forceinline__ void ldsm4(uint32_t* r, uint32_t addr) {
    asm volatile("ldmatrix.sync.aligned.m8n8.x4.shared.b16 {%0,%1,%2,%3}, [%4];"
                 : "=r"(r[0]), "=r"(r[1]), "=r"(r[2]), "=r"(r[3]) : "r"(addr));
}

__device__ __forceinline__ void hmma(float* c, const uint32_t* a, const uint32_t* b) {
    asm("mma.sync.aligned.m16n8k16.row.col.f32.f16.f16.f32 "
        "{%0,%1,%2,%3}, {%4,%5,%6,%7}, {%8,%9}, {%0,%1,%2,%3};"
        : "+f"(c[0]), "+f"(c[1]), "+f"(c[2]), "+f"(c[3])
        : "r"(a[0]), "r"(a[1]), "r"(a[2]), "r"(a[3]), "r"(b[0]), "r"(b[1]));
}

__device__ __forceinline__ uint32_t elect_one() {
    uint32_t pred;
    asm volatile("{\n\t.reg .pred p;\n\telect.sync _|p, 0xFFFFFFFF;\n\t"
                 "selp.b32 %0, 1, 0, p;\n\t}" : "=r"(pred));
    return pred;
}

__device__ __forceinline__ void mbar_wait(uint32_t mbar, uint32_t parity) {
    uint32_t done;
    asm volatile(
        "{\n\t.reg .pred p;\n\t"
        "mbarrier.try_wait.parity.acquire.cta.shared::cta.b64 p, [%1], %2;\n\t"
        "selp.b32 %0, 1, 0, p;\n\t}"
        : "=r"(done) : "r"(mbar), "r"(parity) : "memory");
    while (!done) {
        asm volatile(
            "{\n\t.reg .pred p;\n\t"
            "mbarrier.try_wait.parity.acquire.cta.shared::cta.b64 p, [%1], %2, 0x989680;\n\t"
            "selp.b32 %0, 1, 0, p;\n\t}"
            : "=r"(done) : "r"(mbar), "r"(parity) : "memory");
    }
}

__device__ __forceinline__ void mbar_arrive(uint32_t mbar) {
    asm volatile("mbarrier.arrive.release.cta.shared::cta.b64 _, [%0];"
                 :: "r"(mbar) : "memory");
}

// decode one pair of weights -> packed f16x2 with sign bits merged
__device__ __forceinline__ uint32_t dec_pair(int sa, int sb, int ga, int gb,
                                             float k0, float k1) {
    float fa = ex2(fmaf((float)sa, k1, k0));
    float fb = ex2(fmaf((float)sb, k1, k0));
    __half2 h = __floats2half2_rn(fa, fb);
    uint32_t hb = *(uint32_t*)&h;
    uint32_t sg = (((uint32_t)ga >> 16) & 0x8000u) | ((uint32_t)gb & 0x80000000u);
    return hb | sg;
}

__device__ __forceinline__ void decode8_sts(int4 s0, int4 s1, int4 g0, int4 g1,
                                            uint32_t dst, float k0, float k1) {
    uint32_t p0 = dec_pair(s0.x, s0.y, g0.x, g0.y, k0, k1);
    uint32_t p1 = dec_pair(s0.z, s0.w, g0.z, g0.w, k0, k1);
    uint32_t p2 = dec_pair(s1.x, s1.y, g1.x, g1.y, k0, k1);
    uint32_t p3 = dec_pair(s1.z, s1.w, g1.z, g1.w, k0, k1);
    asm volatile("st.shared.v4.b32 [%0], {%1, %2, %3, %4};"
                 :: "r"(dst), "r"(p0), "r"(p1), "r"(p2), "r"(p3) : "memory");
}

// ---------------- x fp32 -> fp16 pre-pass ----------------
__global__ void __launch_bounds__(256, 1) cvt_x_kernel(const float* __restrict__ x) {
    int i = blockIdx.x * 256 + threadIdx.x;
    float4 v = ((const float4*)x)[i];
    __half2 h0 = __floats2half2_rn(v.x, v.y);
    __half2 h1 = __floats2half2_rn(v.z, v.w);
    uint2 o;
    o.x = *(uint32_t*)&h0;
    o.y = *(uint32_t*)&h1;
    ((uint2*)g_xh)[i] = o;
}

// ---------------- main GEMM kernel (warp-specialized, BK=128) ----------------
__global__ void __launch_bounds__(NT, 1) qins_gemm_kernel(
    const int* __restrict__ stored,
    const int* __restrict__ sign,
    const float* __restrict__ log_min_p,
    const float* __restrict__ log_max_p,
    const float* __restrict__ scale,
    const float* __restrict__ bias,
    float* __restrict__ out)
{
    extern __shared__ char smem_raw[];
    const uint32_t smem_u = (uint32_t)__cvta_generic_to_shared(smem_raw);
    const uint32_t base = (smem_u + 1023u) & ~1023u;

    const int tid  = threadIdx.x;
    const int lane = tid & 31;
    const int wid  = tid >> 5;               // 0..15
    const int o0   = (blockIdx.x >> 1) * TM; // pair CTAs share weights via L2
    const int n0   = (blockIdx.x & 1) * TN;

    if (tid == 0) {
        #pragma unroll
        for (int s = 0; s < NSTAGE; s++) {
            asm volatile("mbarrier.init.shared.b64 [%0], %1;"
                         :: "r"(base + SM_BAR + s * 8), "r"(256u) : "memory");      // full
            asm volatile("mbarrier.init.shared.b64 [%0], %1;"
                         :: "r"(base + SM_BAR + 16 + s * 8), "r"(8u) : "memory");   // empty
        }
    }
    __syncthreads();

    if (wid >= 8) {
        // ================= PRODUCER =================
        const int ptid = tid - 256;
        const float lm = *log_min_p, lx = *log_max_p;
        const float L2E = 1.4426950408889634f;
        const float d  = lx - lm;
        const float k0 = (lm + d * (255.0f / 254.0f)) * L2E;
        const float k1 = (-d * (1.0f / 254.0f)) * L2E;

        const int dm  = ptid >> 2;                 // 0..63
        const int dkq = (ptid & 3) << 4;           // 0,16,32,48 (within 64-wide subtile)
        const uint64_t wrow = (uint64_t)(o0 + dm) * INC;
        const uint32_t a_sts = dm * 128 + (ptid & 3) * 32;

        int stg = 0, eph = 1;                      // empty-wait phase starts flipped

        for (int ch = 0; ch < NCHUNK; ch++) {
            const uint32_t abase = base + SM_A + stg * 16384;
            const uint32_t bbase = base + SM_B + stg * 65536;
            const int k0g = ch * BK;

            mbar_wait(base + SM_BAR + 16 + stg * 8, eph);

            // B: x fp16 via cp.async, two 32KB subtiles, 16 x 16B per thread
            #pragma unroll
            for (int sub = 0; sub < 2; sub++) {
                #pragma unroll
                for (int i = 0; i < 8; i++) {
                    int idx = ptid + i * 256;
                    int row = idx >> 3, col = idx & 7;
                    cpa16(bbase + sub * 32768 + SWZ(row * 128 + col * 16),
                          &g_xh[(size_t)(n0 + row) * INC + k0g + sub * 64 + col * 8]);
                }
            }
            asm volatile("cp.async.commit_group;" ::: "memory");

            // weight LDGs for both subtiles (max MLP), then decode
            const int4* sp0 = (const int4*)(stored + wrow + (size_t)k0g + dkq);
            const int4* gp0 = (const int4*)(sign   + wrow + (size_t)k0g + dkq);
            const int4* sp1 = (const int4*)(stored + wrow + (size_t)k0g + 64 + dkq);
            const int4* gp1 = (const int4*)(sign   + wrow + (size_t)k0g + 64 + dkq);
            int4 a0 = __ldcs(sp0),     a1 = __ldcs(sp0 + 1);
            int4 a2 = __ldcs(sp0 + 2), a3 = __ldcs(sp0 + 3);
            int4 b0 = __ldcs(gp0),     b1 = __ldcs(gp0 + 1);
            int4 b2 = __ldcs(gp0 + 2), b3 = __ldcs(gp0 + 3);
            int4 c0 = __ldcs(sp1),     c1 = __ldcs(sp1 + 1);
            int4 c2 = __ldcs(sp1 + 2), c3 = __ldcs(sp1 + 3);
            int4 d0 = __ldcs(gp1),     d1 = __ldcs(gp1 + 1);
            int4 d2 = __ldcs(gp1 + 2), d3 = __ldcs(gp1 + 3);

            decode8_sts(a0, a1, b0, b1, abase + SWZ(a_sts), k0, k1);
            decode8_sts(a2, a3, b2, b3, abase + SWZ(a_sts + 16), k0, k1);
            decode8_sts(c0, c1, d0, d1, abase + 8192 + SWZ(a_sts), k0, k1);
            decode8_sts(c2, c3, d2, d3, abase + 8192 + SWZ(a_sts + 16), k0, k1);

            // drain B cp.async, then signal this stage full (immediate scheme)
            asm volatile("cp.async.wait_group 0;" ::: "memory");
            mbar_arrive(base + SM_BAR + stg * 8);

            if (++stg == NSTAGE) { stg = 0; eph ^= 1; }
        }

    } else {
        // ================= CONSUMER =================
        const int wm = wid >> 2;                 // 0..1
        const int wn = wid & 3;                  // 0..3
        const int      ar = wm * 32 + (lane & 15);
        const uint32_t ak = (lane & 16) ? 16u : 0u;
        const int      br = wn * 64 + (lane & 7) + ((lane & 16) ? 8 : 0);
        const uint32_t bk = (lane & 8) ? 16u : 0u;

        float acc[2][8][4];
        #pragma unroll
        for (int i = 0; i < 2; i++)
            #pragma unroll
            for (int j = 0; j < 8; j++)
                #pragma unroll
                for (int c = 0; c < 4; c++) acc[i][j][c] = 0.0f;

        int stg = 0, fph = 0;

        for (int ch = 0; ch < NCHUNK; ch++) {
            const uint32_t abase = base + SM_A + stg * 16384;
            const uint32_t bbase = base + SM_B + stg * 65536;

            mbar_wait(base + SM_BAR + stg * 8, fph);

            #pragma unroll
            for (int ks = 0; ks < 8; ks++) {
                const uint32_t asub = abase + (ks >> 2) * 8192  + (ks & 3) * 32;
                const uint32_t bsub = bbase + (ks >> 2) * 32768 + (ks & 3) * 32;
                uint32_t af[2][4], bf[8][2];
                #pragma unroll
                for (int mt = 0; mt < 2; mt++)
                    ldsm4(af[mt], asub + SWZ((ar + mt * 16) * 128) + ((ar + mt * 16) & 0 ? 0 : 0) + (SWZ((ar + mt * 16) * 128 + (ks & 3) * 32 + ak) - SWZ((ar + mt * 16) * 128)) - (ks & 3) * 0);
                // NOTE: the line above must compute SWZ(row*128 + (ks&3)*32 + ak) relative to subtile
                #pragma unroll
                for (int mt = 0; mt < 2; mt++)
                    ldsm4(af[mt], abase + (ks >> 2) * 8192 + SWZ((ar + mt * 16) * 128 + (ks & 3) * 32 + ak));
                #pragma unroll
                for (int pr = 0; pr < 4; pr++) {
                    uint32_t r[4];
                    ldsm4(r, bbase + (ks >> 2) * 32768 + SWZ((br + pr * 16) * 128 + (ks & 3) * 32 + bk));
                    bf[2 * pr][0] = r[0];     bf[2 * pr][1] = r[1];
                    bf[2 * pr + 1][0] = r[2]; bf[2 * pr + 1][1] = r[3];
                }
                #pragma unroll
                for (int mt = 0; mt < 2; mt++)
                    #pragma unroll
                    for (int nt = 0; nt < 8; nt++)
                        hmma(acc[mt][nt], af[mt], bf[nt]);
            }

            __syncwarp();
            if (elect_one())
                mbar_arrive(base + SM_BAR + 16 + stg * 8);
            if (++stg == NSTAGE) { stg = 0; fph ^= 1; }
        }

        // ---- epilogue ----
        #pragma unroll
        for (int mt = 0; mt < 2; mt++) {
            const int ob = o0 + wm * 32 + mt * 16 + (lane >> 2);
            const float b0 = bias[ob],     sc0 = scale[ob];
            const float b8 = bias[ob + 8], sc8 = scale[ob + 8];
            #pragma unroll
            for (int nt = 0; nt < 8; nt++) {
                const int n = n0 + wn * 64 + nt * 8 + (lane & 3) * 2;
                out[(size_t)n       * OUTC + ob]     = (acc[mt][nt][0] + b0) * sc0;
                out[(size_t)(n + 1) * OUTC + ob]     = (acc[mt][nt][1] + b0) * sc0;
                out[(size_t)n       * OUTC + ob + 8] = (acc[mt][nt][2] + b8) * sc8;
                out[(size_t)(n + 1) * OUTC + ob + 8] = (acc[mt][nt][3] + b8) * sc8;
            }
        }
    }
}

extern "C" void kernel_launch(void* const* d_in, const int* in_sizes, int n_in,
                              void* d_out, int out_size) {
    const float* x       = (const float*)d_in[0];
    const int*   stored  = (const int*)d_in[1];
    const int*   sign    = (const int*)d_in[2];
    const float* log_min = (const float*)d_in[3];
    const float* log_max = (const float*)d_in[4];
    const float* scale   = (const float*)d_in[5];
    const float* bias    = (const float*)d_in[6];
    float*       out     = (float*)d_out;

    cudaFuncSetAttribute(qins_gemm_kernel,
                         cudaFuncAttributeMaxDynamicSharedMemorySize, SMEM_BYTES);

    cvt_x_kernel<<<(BATCH * INC / 4) / 256, 256>>>(x);
    qins_gemm_kernel<<<NBLK, NT, SMEM_BYTES>>>(stored, sign, log_min, log_max,
                                               scale, bias, out);
}

// round 14
// speedup vs baseline: 1.0812x; 1.0812x over previous
#include <cuda_runtime.h>
#include <cuda_fp16.h>
#include <cstdint>

#define OUTC 11008
#define INC  4096
#define BATCH 512
#define BK 64
#define NCHUNK (INC / BK)        // 64
#define NT 384                   // 8 consumer warps + 4 producer warps
#define TM 64
#define TN 256
#define NBLK ((OUTC / TM) * (BATCH / TN))   // 344
#define NSTAGE 5

// ---- shared memory (byte offsets from 1024-aligned base) ----
#define SM_BAR   0                       // full[5] @0..39, empty[5] @40..79
#define SM_A     1024                    // 5 stages x 8 KB
#define SM_B     (SM_A + NSTAGE * 8192)  // 41984, 5 stages x 32 KB
#define SM_END   (SM_B + NSTAGE * 32768) // 205824
#define SMEM_BYTES (SM_END + 1024)

__device__ __half g_xh[BATCH * INC];   // fp16 activations (4 MB, L2-resident)

#define SWZ(o) ((o) ^ (((o) >> 3) & 0x70))

__device__ __forceinline__ void cpa16(uint32_t dst, const void* src) {
    asm volatile("cp.async.cg.shared.global [%0], [%1], 16;" :: "r"(dst), "l"(src));
}

__device__ __forceinline__ float ex2(float x) {
    float r;
    asm("ex2.approx.ftz.f32 %0, %1;" : "=f"(r) : "f"(x));
    return r;
}

__device__ __forceinline__ void ldsm4(uint32_t* r, uint32_t addr) {
    asm volatile("ldmatrix.sync.aligned.m8n8.x4.shared.b16 {%0,%1,%2,%3}, [%4];"
                 : "=r"(r[0]), "=r"(r[1]), "=r"(r[2]), "=r"(r[3]) : "r"(addr));
}

__device__ __forceinline__ void hmma(float* c, const uint32_t* a, const uint32_t* b) {
    asm("mma.sync.aligned.m16n8k16.row.col.f32.f16.f16.f32 "
        "{%0,%1,%2,%3}, {%4,%5,%6,%7}, {%8,%9}, {%0,%1,%2,%3};"
        : "+f"(c[0]), "+f"(c[1]), "+f"(c[2]), "+f"(c[3])
        : "r"(a[0]), "r"(a[1]), "r"(a[2]), "r"(a[3]), "r"(b[0]), "r"(b[1]));
}

__device__ __forceinline__ uint32_t elect_one() {
    uint32_t pred;
    asm volatile("{\n\t.reg .pred p;\n\telect.sync _|p, 0xFFFFFFFF;\n\t"
                 "selp.b32 %0, 1, 0, p;\n\t}" : "=r"(pred));
    return pred;
}

__device__ __forceinline__ void mbar_wait(uint32_t mbar, uint32_t parity) {
    uint32_t done;
    asm volatile(
        "{\n\t.reg .pred p;\n\t"
        "mbarrier.try_wait.parity.acquire.cta.shared::cta.b64 p, [%1], %2;\n\t"
        "selp.b32 %0, 1, 0, p;\n\t}"
        : "=r"(done) : "r"(mbar), "r"(parity) : "memory");
    while (!done) {
        asm volatile(
            "{\n\t.reg .pred p;\n\t"
            "mbarrier.try_wait.parity.acquire.cta.shared::cta.b64 p, [%1], %2, 0x989680;\n\t"
            "selp.b32 %0, 1, 0, p;\n\t}"
            : "=r"(done) : "r"(mbar), "r"(parity) : "memory");
    }
}

__device__ __forceinline__ void mbar_arrive(uint32_t mbar) {
    asm volatile("mbarrier.arrive.release.cta.shared::cta.b64 _, [%0];"
                 :: "r"(mbar) : "memory");
}

// decode one pair of weights -> packed f16x2 with sign bits merged
__device__ __forceinline__ uint32_t dec_pair(int sa, int sb, int ga, int gb,
                                             float k0, float k1) {
    float fa = ex2(fmaf((float)sa, k1, k0));
    float fb = ex2(fmaf((float)sb, k1, k0));
    __half2 h = __floats2half2_rn(fa, fb);
    uint32_t hb = *(uint32_t*)&h;
    uint32_t sg = (((uint32_t)ga >> 16) & 0x8000u) | ((uint32_t)gb & 0x80000000u);
    return hb | sg;
}

__device__ __forceinline__ void decode8_sts(int4 s0, int4 s1, int4 g0, int4 g1,
                                            uint32_t dst, float k0, float k1) {
    uint32_t p0 = dec_pair(s0.x, s0.y, g0.x, g0.y, k0, k1);
    uint32_t p1 = dec_pair(s0.z, s0.w, g0.z, g0.w, k0, k1);
    uint32_t p2 = dec_pair(s1.x, s1.y, g1.x, g1.y, k0, k1);
    uint32_t p3 = dec_pair(s1.z, s1.w, g1.z, g1.w, k0, k1);
    asm volatile("st.shared.v4.b32 [%0], {%1, %2, %3, %4};"
                 :: "r"(dst), "r"(p0), "r"(p1), "r"(p2), "r"(p3) : "memory");
}

// ---------------- x fp32 -> fp16 pre-pass ----------------
__global__ void __launch_bounds__(256, 1) cvt_x_kernel(const float* __restrict__ x) {
    int i = blockIdx.x * 256 + threadIdx.x;
    float4 v = ((const float4*)x)[i];
    __half2 h0 = __floats2half2_rn(v.x, v.y);
    __half2 h1 = __floats2half2_rn(v.z, v.w);
    uint2 o;
    o.x = *(uint32_t*)&h0;
    o.y = *(uint32_t*)&h1;
    ((uint2*)g_xh)[i] = o;
}

// ---------------- main GEMM kernel (warp-specialized, 8C + 4P) ----------------
__global__ void __launch_bounds__(NT, 1) qins_gemm_kernel(
    const int* __restrict__ stored,
    const int* __restrict__ sign,
    const float* __restrict__ log_min_p,
    const float* __restrict__ log_max_p,
    const float* __restrict__ scale,
    const float* __restrict__ bias,
    float* __restrict__ out)
{
    extern __shared__ char smem_raw[];
    const uint32_t smem_u = (uint32_t)__cvta_generic_to_shared(smem_raw);
    const uint32_t base = (smem_u + 1023u) & ~1023u;

    const int tid  = threadIdx.x;
    const int lane = tid & 31;
    const int wid  = tid >> 5;               // 0..11
    const int o0   = (blockIdx.x >> 1) * TM; // pair CTAs share weights via L2
    const int n0   = (blockIdx.x & 1) * TN;

    if (tid == 0) {
        #pragma unroll
        for (int s = 0; s < NSTAGE; s++) {
            asm volatile("mbarrier.init.shared.b64 [%0], %1;"
                         :: "r"(base + SM_BAR + s * 8), "r"(128u) : "memory");      // full (128 producer threads)
            asm volatile("mbarrier.init.shared.b64 [%0], %1;"
                         :: "r"(base + SM_BAR + 40 + s * 8), "r"(8u) : "memory");   // empty (8 consumer warps)
        }
    }
    __syncthreads();

    if (wid >= 8) {
        // ================= PRODUCER (4 warps, 128 threads) =================
        const int ptid = tid - 256;                // 0..127
        const float lm = *log_min_p, lx = *log_max_p;
        const float L2E = 1.4426950408889634f;
        const float d  = lx - lm;
        const float k0 = (lm + d * (255.0f / 254.0f)) * L2E;
        const float k1 = (-d * (1.0f / 254.0f)) * L2E;

        // 2 threads per output row, 32 K-elements each
        const int dm  = ptid >> 1;                 // 0..63
        const int dkq = (ptid & 1) << 5;           // 0 or 32
        const uint64_t wrow = (uint64_t)(o0 + dm) * INC;
        const uint32_t a_sts = dm * 128 + (ptid & 1) * 64;   // byte col in A tile

        int stg = 0, eph = 1;                      // empty-wait phase starts flipped
        int prev_full = -1;

        for (int ch = 0; ch < NCHUNK; ch++) {
            const uint32_t abase = base + SM_A + stg * 8192;
            const uint32_t bbase = base + SM_B + stg * 32768;

            mbar_wait(base + SM_BAR + 40 + stg * 8, eph);

            // B: x fp16 via cp.async, 16 x 16B per thread
            #pragma unroll
            for (int i = 0; i < 16; i++) {
                int idx = ptid + i * 128;
                int row = idx >> 3, col = idx & 7;
                cpa16(bbase + SWZ(row * 128 + col * 16),
                      &g_xh[(size_t)(n0 + row) * INC + ch * BK + col * 8]);
            }
            asm volatile("cp.async.commit_group;" ::: "memory");

            // weight LDGs (32 weights = 8+8 int4) + decode into this stage
            const int4* sp = (const int4*)(stored + wrow + (size_t)ch * BK + dkq);
            const int4* gp = (const int4*)(sign   + wrow + (size_t)ch * BK + dkq);
            int4 s0 = __ldcs(sp),     s1 = __ldcs(sp + 1);
            int4 s2 = __ldcs(sp + 2), s3 = __ldcs(sp + 3);
            int4 s4 = __ldcs(sp + 4), s5 = __ldcs(sp + 5);
            int4 s6 = __ldcs(sp + 6), s7 = __ldcs(sp + 7);
            int4 g0 = __ldcs(gp),     g1 = __ldcs(gp + 1);
            int4 g2 = __ldcs(gp + 2), g3 = __ldcs(gp + 3);
            int4 g4 = __ldcs(gp + 4), g5 = __ldcs(gp + 5);
            int4 g6 = __ldcs(gp + 6), g7 = __ldcs(gp + 7);

            decode8_sts(s0, s1, g0, g1, abase + SWZ(a_sts),      k0, k1);
            decode8_sts(s2, s3, g2, g3, abase + SWZ(a_sts + 16), k0, k1);
            decode8_sts(s4, s5, g4, g5, abase + SWZ(a_sts + 32), k0, k1);
            decode8_sts(s6, s7, g6, g7, abase + SWZ(a_sts + 48), k0, k1);

            // signal PREVIOUS stage full (its cp.async group is now drained)
            if (prev_full >= 0) {
                asm volatile("cp.async.wait_group 1;" ::: "memory");
                mbar_arrive(base + SM_BAR + prev_full * 8);
            }
            prev_full = stg;
            if (++stg == NSTAGE) { stg = 0; eph ^= 1; }
        }
        asm volatile("cp.async.wait_group 0;" ::: "memory");
        mbar_arrive(base + SM_BAR + prev_full * 8);

    } else {
        // ================= CONSUMER (8 warps, m32 x n64 each) =================
        const int wm = wid >> 2;                 // 0..1
        const int wn = wid & 3;                  // 0..3
        const int      ar = wm * 32 + (lane & 15);
        const uint32_t ak = (lane & 16) ? 16u : 0u;
        const int      br = wn * 64 + (lane & 7) + ((lane & 16) ? 8 : 0);
        const uint32_t bk = (lane & 8) ? 16u : 0u;

        float acc[2][8][4];
        #pragma unroll
        for (int i = 0; i < 2; i++)
            #pragma unroll
            for (int j = 0; j < 8; j++)
                #pragma unroll
                for (int c = 0; c < 4; c++) acc[i][j][c] = 0.0f;

        int stg = 0, fph = 0;

        for (int ch = 0; ch < NCHUNK; ch++) {
            const uint32_t abase = base + SM_A + stg * 8192;
            const uint32_t bbase = base + SM_B + stg * 32768;

            mbar_wait(base + SM_BAR + stg * 8, fph);

            #pragma unroll
            for (int ks = 0; ks < 4; ks++) {
                uint32_t af[2][4], bf[8][2];
                #pragma unroll
                for (int mt = 0; mt < 2; mt++)
                    ldsm4(af[mt], abase + SWZ((ar + mt * 16) * 128 + ks * 32 + ak));
                #pragma unroll
                for (int pr = 0; pr < 4; pr++) {
                    uint32_t r[4];
                    ldsm4(r, bbase + SWZ((br + pr * 16) * 128 + ks * 32 + bk));
                    bf[2 * pr][0] = r[0];     bf[2 * pr][1] = r[1];
                    bf[2 * pr + 1][0] = r[2]; bf[2 * pr + 1][1] = r[3];
                }
                #pragma unroll
                for (int mt = 0; mt < 2; mt++)
                    #pragma unroll
                    for (int nt = 0; nt < 8; nt++)
                        hmma(acc[mt][nt], af[mt], bf[nt]);
            }

            __syncwarp();
            if (elect_one())
                mbar_arrive(base + SM_BAR + 40 + stg * 8);
            if (++stg == NSTAGE) { stg = 0; fph ^= 1; }
        }

        // ---- epilogue ----
        #pragma unroll
        for (int mt = 0; mt < 2; mt++) {
            const int ob = o0 + wm * 32 + mt * 16 + (lane >> 2);
            const float b0 = bias[ob],     sc0 = scale[ob];
            const float b8 = bias[ob + 8], sc8 = scale[ob + 8];
            #pragma unroll
            for (int nt = 0; nt < 8; nt++) {
                const int n = n0 + wn * 64 + nt * 8 + (lane & 3) * 2;
                out[(size_t)n       * OUTC + ob]     = (acc[mt][nt][0] + b0) * sc0;
                out[(size_t)(n + 1) * OUTC + ob]     = (acc[mt][nt][1] + b0) * sc0;
                out[(size_t)n       * OUTC + ob + 8] = (acc[mt][nt][2] + b8) * sc8;
                out[(size_t)(n + 1) * OUTC + ob + 8] = (acc[mt][nt][3] + b8) * sc8;
            }
        }
    }
}

extern "C" void kernel_launch(void* const* d_in, const int* in_sizes, int n_in,
                              void* d_out, int out_size) {
    const float* x       = (const float*)d_in[0];
    const int*   stored  = (const int*)d_in[1];
    const int*   sign    = (const int*)d_in[2];
    const float* log_min = (const float*)d_in[3];
    const float* log_max = (const float*)d_in[4];
    const float* scale   = (const float*)d_in[5];
    const float* bias    = (const float*)d_in[6];
    float*       out     = (float*)d_out;

    cudaFuncSetAttribute(qins_gemm_kernel,
                         cudaFuncAttributeMaxDynamicSharedMemorySize, SMEM_BYTES);

    cvt_x_kernel<<<(BATCH * INC / 4) / 256, 256>>>(x);
    qins_gemm_kernel<<<NBLK, NT, SMEM_BYTES>>>(stored, sign, log_min, log_max,
                                               scale, bias, out);
}

// round 16
// speedup vs baseline: 1.6967x; 1.5692x over previous
#include <cuda_runtime.h>
#include <cuda_fp16.h>
#include <cstdint>

#define OUTC 11008
#define INC  4096
#define BATCH 512
#define BK 64
#define NCHUNK (INC / BK)        // 64 total; 32 per CTA after K-split
#define NKSPLIT 2
#define CHUNKS_PER (NCHUNK / NKSPLIT)       // 32
#define NT 512                   // 8 consumer warps + 8 producer warps
#define TM 64
#define TN 256
#define NBLK ((OUTC / TM) * (BATCH / TN) * NKSPLIT)   // 172*2*2 = 688
#define NSTAGE 5

// ---- shared memory (byte offsets from 1024-aligned base) ----
#define SM_BAR   0                       // full[5] @0..39, empty[5] @40..79
#define SM_A     1024                    // 5 stages x 8 KB
#define SM_B     (SM_A + NSTAGE * 8192)  // 41984, 5 stages x 32 KB
#define SM_END   (SM_B + NSTAGE * 32768) // 205824
#define SMEM_BYTES (SM_END + 1024)

__device__ __half g_xh[BATCH * INC];   // fp16 activations (4 MB, L2-resident)

#define SWZ(o) ((o) ^ (((o) >> 3) & 0x70))

__device__ __forceinline__ void cpa16(uint32_t dst, const void* src) {
    asm volatile("cp.async.cg.shared.global [%0], [%1], 16;" :: "r"(dst), "l"(src));
}

__device__ __forceinline__ float ex2(float x) {
    float r;
    asm("ex2.approx.ftz.f32 %0, %1;" : "=f"(r) : "f"(x));
    return r;
}

__device__ __forceinline__ void ldsm4(uint32_t* r, uint32_t addr) {
    asm volatile("ldmatrix.sync.aligned.m8n8.x4.shared.b16 {%0,%1,%2,%3}, [%4];"
                 : "=r"(r[0]), "=r"(r[1]), "=r"(r[2]), "=r"(r[3]) : "r"(addr));
}

__device__ __forceinline__ void hmma(float* c, const uint32_t* a, const uint32_t* b) {
    asm("mma.sync.aligned.m16n8k16.row.col.f32.f16.f16.f32 "
        "{%0,%1,%2,%3}, {%4,%5,%6,%7}, {%8,%9}, {%0,%1,%2,%3};"
        : "+f"(c[0]), "+f"(c[1]), "+f"(c[2]), "+f"(c[3])
        : "r"(a[0]), "r"(a[1]), "r"(a[2]), "r"(a[3]), "r"(b[0]), "r"(b[1]));
}

__device__ __forceinline__ uint32_t elect_one() {
    uint32_t pred;
    asm volatile("{\n\t.reg .pred p;\n\telect.sync _|p, 0xFFFFFFFF;\n\t"
                 "selp.b32 %0, 1, 0, p;\n\t}" : "=r"(pred));
    return pred;
}

__device__ __forceinline__ void mbar_wait(uint32_t mbar, uint32_t parity) {
    uint32_t done;
    asm volatile(
        "{\n\t.reg .pred p;\n\t"
        "mbarrier.try_wait.parity.acquire.cta.shared::cta.b64 p, [%1], %2;\n\t"
        "selp.b32 %0, 1, 0, p;\n\t}"
        : "=r"(done) : "r"(mbar), "r"(parity) : "memory");
    while (!done) {
        asm volatile(
            "{\n\t.reg .pred p;\n\t"
            "mbarrier.try_wait.parity.acquire.cta.shared::cta.b64 p, [%1], %2, 0x989680;\n\t"
            "selp.b32 %0, 1, 0, p;\n\t}"
            : "=r"(done) : "r"(mbar), "r"(parity) : "memory");
    }
}

__device__ __forceinline__ void mbar_arrive(uint32_t mbar) {
    asm volatile("mbarrier.arrive.release.cta.shared::cta.b64 _, [%0];"
                 :: "r"(mbar) : "memory");
}

__device__ __forceinline__ void red_add(float* p, float v) {
    asm volatile("red.global.add.f32 [%0], %1;" :: "l"(p), "f"(v) : "memory");
}

// decode one pair of weights -> packed f16x2 with sign bits merged
__device__ __forceinline__ uint32_t dec_pair(int sa, int sb, int ga, int gb,
                                             float k0, float k1) {
    float fa = ex2(fmaf((float)sa, k1, k0));
    float fb = ex2(fmaf((float)sb, k1, k0));
    __half2 h = __floats2half2_rn(fa, fb);
    uint32_t hb = *(uint32_t*)&h;
    uint32_t sg = (((uint32_t)ga >> 16) & 0x8000u) | ((uint32_t)gb & 0x80000000u);
    return hb | sg;
}

__device__ __forceinline__ void decode8_sts(int4 s0, int4 s1, int4 g0, int4 g1,
                                            uint32_t dst, float k0, float k1) {
    uint32_t p0 = dec_pair(s0.x, s0.y, g0.x, g0.y, k0, k1);
    uint32_t p1 = dec_pair(s0.z, s0.w, g0.z, g0.w, k0, k1);
    uint32_t p2 = dec_pair(s1.x, s1.y, g1.x, g1.y, k0, k1);
    uint32_t p3 = dec_pair(s1.z, s1.w, g1.z, g1.w, k0, k1);
    asm volatile("st.shared.v4.b32 [%0], {%1, %2, %3, %4};"
                 :: "r"(dst), "r"(p0), "r"(p1), "r"(p2), "r"(p3) : "memory");
}

// ---------------- x fp32 -> fp16 pre-pass ----------------
__global__ void __launch_bounds__(256, 1) cvt_x_kernel(const float* __restrict__ x) {
    int i = blockIdx.x * 256 + threadIdx.x;
    float4 v = ((const float4*)x)[i];
    __half2 h0 = __floats2half2_rn(v.x, v.y);
    __half2 h1 = __floats2half2_rn(v.z, v.w);
    uint2 o;
    o.x = *(uint32_t*)&h0;
    o.y = *(uint32_t*)&h1;
    ((uint2*)g_xh)[i] = o;
}

// ---------------- out init: out[n][o] = bias[o] * scale[o] ----------------
__global__ void __launch_bounds__(256, 4) init_out_kernel(
    const float* __restrict__ scale, const float* __restrict__ bias,
    float* __restrict__ out) {
    const int o = blockIdx.x * 256 + threadIdx.x;   // OUTC = 43 * 256
    const int n = blockIdx.y;
    out[(size_t)n * OUTC + o] = bias[o] * scale[o];
}

// ---------------- main GEMM kernel (warp-specialized, K-split x2) ----------------
__global__ void __launch_bounds__(NT, 1) qins_gemm_kernel(
    const int* __restrict__ stored,
    const int* __restrict__ sign,
    const float* __restrict__ log_min_p,
    const float* __restrict__ log_max_p,
    const float* __restrict__ scale,
    float* __restrict__ out)
{
    extern __shared__ char smem_raw[];
    const uint32_t smem_u = (uint32_t)__cvta_generic_to_shared(smem_raw);
    const uint32_t base = (smem_u + 1023u) & ~1023u;

    const int tid  = threadIdx.x;
    const int lane = tid & 31;
    const int wid  = tid >> 5;               // 0..15
    // bid = mb*4 + nh*2 + kh : the two CTAs with identical weights (same mb,kh,
    // differing nh) are 2 apart -> co-scheduled -> L2 dedupe of weight stream
    const int bid  = blockIdx.x;
    const int o0   = (bid >> 2) * TM;
    const int n0   = ((bid >> 1) & 1) * TN;
    const int kh   = bid & 1;
    const int ch0  = kh * CHUNKS_PER;

    if (tid == 0) {
        #pragma unroll
        for (int s = 0; s < NSTAGE; s++) {
            asm volatile("mbarrier.init.shared.b64 [%0], %1;"
                         :: "r"(base + SM_BAR + s * 8), "r"(256u) : "memory");      // full
            asm volatile("mbarrier.init.shared.b64 [%0], %1;"
                         :: "r"(base + SM_BAR + 40 + s * 8), "r"(8u) : "memory");   // empty
        }
    }
    __syncthreads();

    if (wid >= 8) {
        // ================= PRODUCER =================
        const int ptid = tid - 256;
        const float lm = *log_min_p, lx = *log_max_p;
        const float L2E = 1.4426950408889634f;
        const float d  = lx - lm;
        const float k0 = (lm + d * (255.0f / 254.0f)) * L2E;
        const float k1 = (-d * (1.0f / 254.0f)) * L2E;

        const int dm  = ptid >> 2;                 // 0..63
        const int dkq = (ptid & 3) << 4;           // 0,16,32,48
        const uint64_t wrow = (uint64_t)(o0 + dm) * INC;
        const uint32_t a_sts = dm * 128 + (ptid & 3) * 32;

        int stg = 0, eph = 1;                      // empty-wait phase starts flipped
        int prev_full = -1;

        for (int it = 0; it < CHUNKS_PER; it++) {
            const int ch = ch0 + it;
            const uint32_t abase = base + SM_A + stg * 8192;
            const uint32_t bbase = base + SM_B + stg * 32768;

            mbar_wait(base + SM_BAR + 40 + stg * 8, eph);

            // B: x fp16 via cp.async, 8 x 16B per thread
            #pragma unroll
            for (int i = 0; i < 8; i++) {
                int idx = ptid + i * 256;
                int row = idx >> 3, col = idx & 7;
                cpa16(bbase + SWZ(row * 128 + col * 16),
                      &g_xh[(size_t)(n0 + row) * INC + ch * BK + col * 8]);
            }
            asm volatile("cp.async.commit_group;" ::: "memory");

            // weight LDGs + decode into this stage
            const int4* sp = (const int4*)(stored + wrow + (size_t)ch * BK + dkq);
            const int4* gp = (const int4*)(sign   + wrow + (size_t)ch * BK + dkq);
            int4 s0 = __ldcs(sp),     s1 = __ldcs(sp + 1);
            int4 g0 = __ldcs(gp),     g1 = __ldcs(gp + 1);
            int4 s2 = __ldcs(sp + 2), s3 = __ldcs(sp + 3);
            int4 g2 = __ldcs(gp + 2), g3 = __ldcs(gp + 3);

            decode8_sts(s0, s1, g0, g1, abase + SWZ(a_sts), k0, k1);
            decode8_sts(s2, s3, g2, g3, abase + SWZ(a_sts + 16), k0, k1);

            // signal PREVIOUS stage full (its cp.async group is now drained)
            if (prev_full >= 0) {
                asm volatile("cp.async.wait_group 1;" ::: "memory");
                mbar_arrive(base + SM_BAR + prev_full * 8);
            }
            prev_full = stg;
            if (++stg == NSTAGE) { stg = 0; eph ^= 1; }
        }
        asm volatile("cp.async.wait_group 0;" ::: "memory");
        mbar_arrive(base + SM_BAR + prev_full * 8);

    } else {
        // ================= CONSUMER =================
        const int wm = wid >> 2;                 // 0..1
        const int wn = wid & 3;                  // 0..3
        const int      ar = wm * 32 + (lane & 15);
        const uint32_t ak = (lane & 16) ? 16u : 0u;
        const int      br = wn * 64 + (lane & 7) + ((lane & 16) ? 8 : 0);
        const uint32_t bk = (lane & 8) ? 16u : 0u;

        float acc[2][8][4];
        #pragma unroll
        for (int i = 0; i < 2; i++)
            #pragma unroll
            for (int j = 0; j < 8; j++)
                #pragma unroll
                for (int c = 0; c < 4; c++) acc[i][j][c] = 0.0f;

        int stg = 0, fph = 0;

        for (int it = 0; it < CHUNKS_PER; it++) {
            const uint32_t abase = base + SM_A + stg * 8192;
            const uint32_t bbase = base + SM_B + stg * 32768;

            mbar_wait(base + SM_BAR + stg * 8, fph);

            #pragma unroll
            for (int ks = 0; ks < 4; ks++) {
                uint32_t af[2][4], bf[8][2];
                #pragma unroll
                for (int mt = 0; mt < 2; mt++)
                    ldsm4(af[mt], abase + SWZ((ar + mt * 16) * 128 + ks * 32 + ak));
                #pragma unroll
                for (int pr = 0; pr < 4; pr++) {
                    uint32_t r[4];
                    ldsm4(r, bbase + SWZ((br + pr * 16) * 128 + ks * 32 + bk));
                    bf[2 * pr][0] = r[0];     bf[2 * pr][1] = r[1];
                    bf[2 * pr + 1][0] = r[2]; bf[2 * pr + 1][1] = r[3];
                }
                #pragma unroll
                for (int mt = 0; mt < 2; mt++)
                    #pragma unroll
                    for (int nt = 0; nt < 8; nt++)
                        hmma(acc[mt][nt], af[mt], bf[nt]);
            }

            __syncwarp();
            if (elect_one())
                mbar_arrive(base + SM_BAR + 40 + stg * 8);
            if (++stg == NSTAGE) { stg = 0; fph ^= 1; }
        }

        // ---- epilogue: out += acc * scale (bias*scale pre-written by init) ----
        #pragma unroll
        for (int mt = 0; mt < 2; mt++) {
            const int ob = o0 + wm * 32 + mt * 16 + (lane >> 2);
            const float sc0 = scale[ob];
            const float sc8 = scale[ob + 8];
            #pragma unroll
            for (int nt = 0; nt < 8; nt++) {
                const int n = n0 + wn * 64 + nt * 8 + (lane & 3) * 2;
                red_add(&out[(size_t)n       * OUTC + ob],     acc[mt][nt][0] * sc0);
                red_add(&out[(size_t)(n + 1) * OUTC + ob],     acc[mt][nt][1] * sc0);
                red_add(&out[(size_t)n       * OUTC + ob + 8], acc[mt][nt][2] * sc8);
                red_add(&out[(size_t)(n + 1) * OUTC + ob + 8], acc[mt][nt][3] * sc8);
            }
        }
    }
}

extern "C" void kernel_launch(void* const* d_in, const int* in_sizes, int n_in,
                              void* d_out, int out_size) {
    const float* x       = (const float*)d_in[0];
    const int*   stored  = (const int*)d_in[1];
    const int*   sign    = (const int*)d_in[2];
    const float* log_min = (const float*)d_in[3];
    const float* log_max = (const float*)d_in[4];
    const float* scale   = (const float*)d_in[5];
    const float* bias    = (const float*)d_in[6];
    float*       out     = (float*)d_out;

    cudaFuncSetAttribute(qins_gemm_kernel,
                         cudaFuncAttributeMaxDynamicSharedMemorySize, SMEM_BYTES);

    cvt_x_kernel<<<(BATCH * INC / 4) / 256, 256>>>(x);
    dim3 ig(OUTC / 256, BATCH);
    init_out_kernel<<<ig, 256>>>(scale, bias, out);
    qins_gemm_kernel<<<NBLK, NT, SMEM_BYTES>>>(stored, sign, log_min, log_max,
                                               scale, out);
}